// round 3
// baseline (speedup 1.0000x reference)
#include <cuda_runtime.h>
#include <cuda_bf16.h>
#include <math.h>

// Problem constants
#define Bn   128
#define Un   2048
#define Kn   2
#define Nn   4
#define Ln   512
#define UK   (Un / Kn)        // 1024
#define UN   (Un / Nn)        // 512
#define XHW  (3 * UK)         // 3072 per-k width
#define KD   (Kn * XHW)       // 6144 total GEMM K-dim
#define OW   (4 * Un)         // 8192 ifgo width (N * 4U/N)
#define NW   (4 * UN)         // 2048 per-n ifgo chunk

// Output layout (flattened concat of return tuple)
#define XOUT_OFF 0                       // [B, 2U]
#define HOUT_OFF (Bn * 2 * Un)           // [B, U]
#define COUT_OFF (Bn * 3 * Un)           // [B, U]
#define CTX_OFF  (Bn * 4 * Un)           // [B, U]

// Scratch (no allocations allowed)
__device__ float g_xh[Bn * KD];     // packed [h_k | x_k | ctx_k] per k-chunk
__device__ float g_ifgo[Bn * OW];   // GEMM result

__device__ __forceinline__ float sigmoidf(float v) {
    return 1.0f / (1.0f + expf(-v));
}

// ---------------------------------------------------------------------------
// 1) Pack XH[b, k*3072 + d]: d<1024 -> h, d<2048 -> x, else context
// ---------------------------------------------------------------------------
__global__ void pack_xh_kernel(const float* __restrict__ x,
                               const float* __restrict__ h,
                               const float* __restrict__ ctx) {
    int idx = blockIdx.x * blockDim.x + threadIdx.x;
    if (idx >= Bn * KD) return;
    int b  = idx / KD;
    int kd = idx - b * KD;
    int k  = kd / XHW;
    int d  = kd - k * XHW;
    int off = b * Un + k * UK;
    float v;
    if (d < UK)            v = h[off + d];
    else if (d < 2 * UK)   v = x[off + d - UK];
    else                   v = ctx[off + d - 2 * UK];
    g_xh[idx] = v;
}

// ---------------------------------------------------------------------------
// 2) SGEMM: ifgo[128, 8192] = XH[128, 6144] @ Wbig[6144, 8192]
//    Wbig column block (within one n-chunk) comes from W[(k*N+n), d, f].
//    BM=128 (all of B), BN=64, BK=16, 256 threads, 8x4 register tile.
// ---------------------------------------------------------------------------
__global__ void __launch_bounds__(256)
gemm_ifgo_kernel(const float* __restrict__ W) {
    __shared__ float As[16][128];     // [k][m]
    __shared__ float Bs[16][68];      // [k][n] (padded)

    const int tid  = threadIdx.x;
    const int col0 = blockIdx.x * 64;         // 0..8128
    const int n    = col0 >> 11;              // /2048
    const int f0   = col0 & (NW - 1);

    const int tx = tid & 15;                  // 0..15
    const int ty = tid >> 4;                  // 0..15
    const int r0 = ty * 8;                    // output rows r0..r0+7
    const int c0 = tx * 4;                    // output cols c0..c0+3 (local)

    float acc[8][4];
#pragma unroll
    for (int i = 0; i < 8; ++i)
#pragma unroll
        for (int j = 0; j < 4; ++j) acc[i][j] = 0.0f;

    // A-load mapping: 2 float4 per thread
    const int fi0 = tid * 2;

    for (int kt = 0; kt < KD / 16; ++kt) {
        const int kk0 = kt << 4;
        const int k   = (kk0 >= XHW) ? 1 : 0;
        const int d   = kk0 - k * XHW;

        // Load A tile [128 x 16] (transposed into As[k][m])
#pragma unroll
        for (int i = 0; i < 2; ++i) {
            int fi = fi0 + i;
            int r  = fi >> 2;
            int cc = (fi & 3) << 2;
            float4 v = *reinterpret_cast<const float4*>(&g_xh[r * KD + kk0 + cc]);
            As[cc + 0][r] = v.x;
            As[cc + 1][r] = v.y;
            As[cc + 2][r] = v.z;
            As[cc + 3][r] = v.w;
        }
        // Load B tile [16 x 64]
        {
            const float* wb = W + ((size_t)(k * Nn + n) * XHW + d) * (size_t)NW + f0;
            int r  = tid >> 4;
            int cc = (tid & 15) << 2;
            float4 wv = *reinterpret_cast<const float4*>(wb + r * NW + cc);
            *reinterpret_cast<float4*>(&Bs[r][cc]) = wv;
        }
        __syncthreads();

#pragma unroll
        for (int kk = 0; kk < 16; ++kk) {
            float4 a0 = *reinterpret_cast<const float4*>(&As[kk][r0]);
            float4 a1 = *reinterpret_cast<const float4*>(&As[kk][r0 + 4]);
            float4 bv = *reinterpret_cast<const float4*>(&Bs[kk][c0]);
            float a[8] = {a0.x, a0.y, a0.z, a0.w, a1.x, a1.y, a1.z, a1.w};
            float bb[4] = {bv.x, bv.y, bv.z, bv.w};
#pragma unroll
            for (int i = 0; i < 8; ++i)
#pragma unroll
                for (int j = 0; j < 4; ++j)
                    acc[i][j] = fmaf(a[i], bb[j], acc[i][j]);
        }
        __syncthreads();
    }

#pragma unroll
    for (int i = 0; i < 8; ++i) {
        float4 o = make_float4(acc[i][0], acc[i][1], acc[i][2], acc[i][3]);
        *reinterpret_cast<float4*>(&g_ifgo[(r0 + i) * OW + col0 + c0]) = o;
    }
}

// ---------------------------------------------------------------------------
// 3) Gates + cell update + output concat
//    h_out -> out[HOUT], c_out -> out[COUT], x_out = [h_out | context]
// ---------------------------------------------------------------------------
__global__ void gates_kernel(const float* __restrict__ c,
                             const float* __restrict__ ctx,
                             float* __restrict__ out) {
    int idx = blockIdx.x * blockDim.x + threadIdx.x;
    if (idx >= Bn * Un) return;
    int b = idx >> 11;            // /2048
    int u = idx & (Un - 1);
    int n = u >> 9;               // /512
    int j = u & (UN - 1);
    const float* base = g_ifgo + (size_t)b * OW + n * NW + j;
    float iv = sigmoidf(base[0]);
    float fv = sigmoidf(base[512]);
    float gv = tanhf(base[1024]);
    float ov = sigmoidf(base[1536]);
    float cv = c[idx];
    float nc = fv * cv + iv * gv;
    float nh = ov * tanhf(nc);
    out[HOUT_OFF + idx] = nh;
    out[COUT_OFF + idx] = nc;
    out[XOUT_OFF + b * (2 * Un) + u]      = nh;
    out[XOUT_OFF + b * (2 * Un) + Un + u] = ctx[idx];
}

// ---------------------------------------------------------------------------
// 4) Attention: one block per batch row.
//    Phase 1: warp-per-l dots -> scores[512]; block softmax.
//    Phase 2: column-owned weighted sum over enc_out -> new_ctx.
// ---------------------------------------------------------------------------
__global__ void __launch_bounds__(512)
attn_kernel(const float* __restrict__ enc_attn,
            const float* __restrict__ enc_out,
            float* __restrict__ out) {
    __shared__ float sh_h[Un];        // h_out row (8 KB)
    __shared__ float sc[Ln];          // scores (2 KB)
    __shared__ float red[16];
    __shared__ float red1;

    const int b    = blockIdx.x;
    const int tid  = threadIdx.x;
    const int lane = tid & 31;
    const int warp = tid >> 5;        // 0..15

    // Load h_out row into shared (512 threads x float4 = 2048 floats)
    const float* hb = out + HOUT_OFF + (size_t)b * Un;
    reinterpret_cast<float4*>(sh_h)[tid] = reinterpret_cast<const float4*>(hb)[tid];
    __syncthreads();

    // Phase 1: scores[l] = dot(enc_attn[b,l,:], h_out[b,:])
    const float* ea = enc_attn + (size_t)b * Ln * Un;
    const float4* sh4 = reinterpret_cast<const float4*>(sh_h);
    for (int l = warp; l < Ln; l += 16) {
        const float4* row = reinterpret_cast<const float4*>(ea + (size_t)l * Un);
        float s = 0.0f;
#pragma unroll 4
        for (int it = lane; it < Un / 4; it += 32) {
            float4 v = row[it];
            float4 hv = sh4[it];
            s += v.x * hv.x + v.y * hv.y + v.z * hv.z + v.w * hv.w;
        }
#pragma unroll
        for (int o = 16; o > 0; o >>= 1)
            s += __shfl_xor_sync(0xffffffffu, s, o);
        if (lane == 0) sc[l] = s;
    }
    __syncthreads();

    // Softmax over 512 scores
    float v = sc[tid];
    float m = v;
#pragma unroll
    for (int o = 16; o > 0; o >>= 1)
        m = fmaxf(m, __shfl_xor_sync(0xffffffffu, m, o));
    if (lane == 0) red[warp] = m;
    __syncthreads();
    if (tid == 0) {
        float mm = red[0];
#pragma unroll
        for (int i = 1; i < 16; ++i) mm = fmaxf(mm, red[i]);
        red1 = mm;
    }
    __syncthreads();
    float e = expf(v - red1);
    float s = e;
#pragma unroll
    for (int o = 16; o > 0; o >>= 1)
        s += __shfl_xor_sync(0xffffffffu, s, o);
    if (lane == 0) red[warp] = s;
    __syncthreads();
    if (tid == 0) {
        float ss = 0.0f;
#pragma unroll
        for (int i = 0; i < 16; ++i) ss += red[i];
        red1 = ss;
    }
    __syncthreads();
    sc[tid] = e / red1;
    __syncthreads();

    // Phase 2: new_ctx[b, u] = sum_l sc[l] * enc_out[b, l, u]
    const float* eo = enc_out + (size_t)b * Ln * Un;
    float4 acc = make_float4(0.f, 0.f, 0.f, 0.f);
#pragma unroll 4
    for (int l = 0; l < Ln; ++l) {
        float w = sc[l];
        float4 vv = reinterpret_cast<const float4*>(eo + (size_t)l * Un)[tid];
        acc.x = fmaf(w, vv.x, acc.x);
        acc.y = fmaf(w, vv.y, acc.y);
        acc.z = fmaf(w, vv.z, acc.z);
        acc.w = fmaf(w, vv.w, acc.w);
    }
    reinterpret_cast<float4*>(out + CTX_OFF + (size_t)b * Un)[tid] = acc;
}

// ---------------------------------------------------------------------------
extern "C" void kernel_launch(void* const* d_in, const int* in_sizes, int n_in,
                              void* d_out, int out_size) {
    const float* x        = (const float*)d_in[0];
    const float* h        = (const float*)d_in[1];
    const float* c        = (const float*)d_in[2];
    const float* context  = (const float*)d_in[3];
    const float* W        = (const float*)d_in[4];
    const float* enc_attn = (const float*)d_in[5];
    const float* enc_out  = (const float*)d_in[6];
    float* out = (float*)d_out;

    pack_xh_kernel<<<(Bn * KD + 255) / 256, 256>>>(x, h, context);
    gemm_ifgo_kernel<<<OW / 64, 256>>>(W);
    gates_kernel<<<(Bn * Un + 255) / 256, 256>>>(c, context, out);
    attn_kernel<<<Bn, 512>>>(enc_attn, enc_out, out);
}

// round 4
// speedup vs baseline: 1.2669x; 1.2669x over previous
#include <cuda_runtime.h>
#include <cuda_bf16.h>
#include <math.h>
#include <stdint.h>

// Problem constants
#define Bn   128
#define Un   2048
#define Kn   2
#define Nn   4
#define Ln   512
#define UK   (Un / Kn)        // 1024
#define UN   (Un / Nn)        // 512
#define XHW  (3 * UK)         // 3072 per-k width
#define KD   (Kn * XHW)       // 6144 total GEMM K-dim
#define OW   (4 * Un)         // 8192 ifgo width
#define NW   (4 * UN)         // 2048 per-n ifgo chunk
#define KHALF 3072            // split-K half (== XHW, aligns with k-chunk)

// Output layout
#define XOUT_OFF 0                       // [B, 2U]
#define HOUT_OFF (Bn * 2 * Un)           // [B, U]
#define COUT_OFF (Bn * 3 * Un)           // [B, U]
#define CTX_OFF  (Bn * 4 * Un)           // [B, U]

// Scratch
__device__ float g_xh_hi[Bn * KD];            // tf32 hi part of packed input
__device__ float g_xh_lo[Bn * KD];            // tf32 lo part
__device__ float g_part[2 * Bn * OW];         // split-K partial sums (8 MB)
__device__ float g_score[Bn * Ln];            // attention scores / weights

__device__ __forceinline__ float sigmoidf(float v) {
    return 1.0f / (1.0f + expf(-v));
}

__device__ __forceinline__ float tf32_rna(float x) {
    uint32_t u;
    asm("cvt.rna.tf32.f32 %0, %1;" : "=r"(u) : "f"(x));
    return __uint_as_float(u);
}

__device__ __forceinline__ void mma_tf32(float* d, const uint32_t* a, const uint32_t* b) {
    asm volatile(
        "mma.sync.aligned.m16n8k8.row.col.f32.tf32.tf32.f32 "
        "{%0,%1,%2,%3}, {%4,%5,%6,%7}, {%8,%9}, {%0,%1,%2,%3};\n"
        : "+f"(d[0]), "+f"(d[1]), "+f"(d[2]), "+f"(d[3])
        : "r"(a[0]), "r"(a[1]), "r"(a[2]), "r"(a[3]), "r"(b[0]), "r"(b[1]));
}

// ---------------------------------------------------------------------------
// 1) Pack XH and pre-split into tf32 hi/lo
// ---------------------------------------------------------------------------
__global__ void pack_xh_kernel(const float* __restrict__ x,
                               const float* __restrict__ h,
                               const float* __restrict__ ctx) {
    int idx = blockIdx.x * blockDim.x + threadIdx.x;
    if (idx >= Bn * KD) return;
    int b  = idx / KD;
    int kd = idx - b * KD;
    int k  = kd / XHW;
    int d  = kd - k * XHW;
    int off = b * Un + k * UK;
    float v;
    if (d < UK)            v = h[off + d];
    else if (d < 2 * UK)   v = x[off + d - UK];
    else                   v = ctx[off + d - 2 * UK];
    float hi = tf32_rna(v);
    float lo = tf32_rna(v - hi);
    g_xh_hi[idx] = hi;
    g_xh_lo[idx] = lo;
}

// ---------------------------------------------------------------------------
// 2) 3xTF32 tensor-core GEMM: part[kz] = XH[:, kz*3072:(kz+1)*3072] @ Wslice
//    BM=128, BN=128, BK=8, 256 threads (8 warps: 2 along M x 4 along N),
//    warp tile 64x32 via m16n8k8, double-buffered smem, split-K = 2.
// ---------------------------------------------------------------------------
#define GBK   8
#define ASTR  12          // A smem row stride (pad for conflict-free frags)
#define BSTR  136         // B smem row stride
#define ASZ   (128 * ASTR)        // 1536 floats
#define BSZ   (GBK * BSTR)        // 1088 floats
#define AH_OFF 0
#define AL_OFF ASZ
#define BH_OFF (2 * ASZ)
#define BL_OFF (2 * ASZ + BSZ)
#define SST   (2 * ASZ + 2 * BSZ) // 5248 floats per stage
#define GNIT  (KHALF / GBK)       // 384 iterations

__global__ void __launch_bounds__(256, 1)
gemm_tf32_kernel(const float* __restrict__ W) {
    __shared__ float sm[2 * SST];     // ~42 KB

    const int tid  = threadIdx.x;
    const int lane = tid & 31;
    const int warp = tid >> 5;
    const int wm   = warp & 1;         // 0..1 (M)
    const int wn   = warp >> 1;        // 0..3 (N)

    const int col0 = blockIdx.x * 128; // global output column base
    const int kz   = blockIdx.y;       // split-K index (== k-chunk)
    const int n    = col0 >> 11;       // n-chunk of this column block
    const int f0   = col0 & (NW - 1);

    // Global load mappings
    const int rA  = tid >> 1;                 // 0..127
    const int cA  = (tid & 1) << 2;           // 0 or 4
    const int rB  = tid >> 5;                 // 0..7
    const int cB  = (tid & 31) << 2;          // 0..124

    const float* aH = g_xh_hi + (size_t)rA * KD + kz * KHALF + cA;
    const float* aL = g_xh_lo + (size_t)rA * KD + kz * KHALF + cA;
    const float* wP = W + ((size_t)(kz * Nn + n) * XHW) * (size_t)NW + f0
                        + (size_t)rB * NW + cB;

    float acc[4][4][4];
#pragma unroll
    for (int i = 0; i < 4; ++i)
#pragma unroll
        for (int j = 0; j < 4; ++j)
#pragma unroll
            for (int q = 0; q < 4; ++q) acc[i][j][q] = 0.0f;

    float4 pah, pal, pw;

    // prologue: load k-tile 0
    pah = *reinterpret_cast<const float4*>(aH);
    pal = *reinterpret_cast<const float4*>(aL);
    pw  = *reinterpret_cast<const float4*>(wP);
    {
        float* s = sm;  // stage 0
        *reinterpret_cast<float4*>(&s[AH_OFF + rA * ASTR + cA]) = pah;
        *reinterpret_cast<float4*>(&s[AL_OFF + rA * ASTR + cA]) = pal;
        float4 whv, wlv;
        whv.x = tf32_rna(pw.x); wlv.x = tf32_rna(pw.x - whv.x);
        whv.y = tf32_rna(pw.y); wlv.y = tf32_rna(pw.y - whv.y);
        whv.z = tf32_rna(pw.z); wlv.z = tf32_rna(pw.z - whv.z);
        whv.w = tf32_rna(pw.w); wlv.w = tf32_rna(pw.w - whv.w);
        *reinterpret_cast<float4*>(&s[BH_OFF + rB * BSTR + cB]) = whv;
        *reinterpret_cast<float4*>(&s[BL_OFF + rB * BSTR + cB]) = wlv;
    }
    __syncthreads();

    const int kr = lane & 3;
    const int gq = lane >> 2;

    for (int it = 0; it < GNIT; ++it) {
        const int cur = it & 1;
        if (it + 1 < GNIT) {
            const size_t ko = (size_t)(it + 1) * GBK;
            pah = *reinterpret_cast<const float4*>(aH + ko);
            pal = *reinterpret_cast<const float4*>(aL + ko);
            pw  = *reinterpret_cast<const float4*>(wP + ko * NW);
        }

        // ---- compute on stage cur ----
        {
            const float* AsH = sm + cur * SST + AH_OFF;
            const float* AsL = sm + cur * SST + AL_OFF;
            const float* BsH = sm + cur * SST + BH_OFF;
            const float* BsL = sm + cur * SST + BL_OFF;

            uint32_t bh[4][2], bl[4][2];
#pragma unroll
            for (int nt = 0; nt < 4; ++nt) {
                int nb = wn * 32 + nt * 8 + gq;
                bh[nt][0] = __float_as_uint(BsH[kr * BSTR + nb]);
                bh[nt][1] = __float_as_uint(BsH[(kr + 4) * BSTR + nb]);
                bl[nt][0] = __float_as_uint(BsL[kr * BSTR + nb]);
                bl[nt][1] = __float_as_uint(BsL[(kr + 4) * BSTR + nb]);
            }
#pragma unroll
            for (int mt = 0; mt < 4; ++mt) {
                int mr = wm * 64 + mt * 16 + gq;
                uint32_t ah[4], al[4];
                ah[0] = __float_as_uint(AsH[mr * ASTR + kr]);
                ah[1] = __float_as_uint(AsH[(mr + 8) * ASTR + kr]);
                ah[2] = __float_as_uint(AsH[mr * ASTR + kr + 4]);
                ah[3] = __float_as_uint(AsH[(mr + 8) * ASTR + kr + 4]);
                al[0] = __float_as_uint(AsL[mr * ASTR + kr]);
                al[1] = __float_as_uint(AsL[(mr + 8) * ASTR + kr]);
                al[2] = __float_as_uint(AsL[mr * ASTR + kr + 4]);
                al[3] = __float_as_uint(AsL[(mr + 8) * ASTR + kr + 4]);
#pragma unroll
                for (int nt = 0; nt < 4; ++nt) {
                    mma_tf32(acc[mt][nt], ah, bh[nt]);   // hi*hi
                    mma_tf32(acc[mt][nt], ah, bl[nt]);   // hi*lo
                    mma_tf32(acc[mt][nt], al, bh[nt]);   // lo*hi
                }
            }
        }

        // ---- store prefetched tile into next stage ----
        if (it + 1 < GNIT) {
            float* s = sm + (cur ^ 1) * SST;
            *reinterpret_cast<float4*>(&s[AH_OFF + rA * ASTR + cA]) = pah;
            *reinterpret_cast<float4*>(&s[AL_OFF + rA * ASTR + cA]) = pal;
            float4 whv, wlv;
            whv.x = tf32_rna(pw.x); wlv.x = tf32_rna(pw.x - whv.x);
            whv.y = tf32_rna(pw.y); wlv.y = tf32_rna(pw.y - whv.y);
            whv.z = tf32_rna(pw.z); wlv.z = tf32_rna(pw.z - whv.z);
            whv.w = tf32_rna(pw.w); wlv.w = tf32_rna(pw.w - whv.w);
            *reinterpret_cast<float4*>(&s[BH_OFF + rB * BSTR + cB]) = whv;
            *reinterpret_cast<float4*>(&s[BL_OFF + rB * BSTR + cB]) = wlv;
        }
        __syncthreads();
    }

    // Epilogue: write partials
    float* op = g_part + (size_t)kz * (Bn * OW) + col0;
#pragma unroll
    for (int mt = 0; mt < 4; ++mt) {
#pragma unroll
        for (int nt = 0; nt < 4; ++nt) {
            int r = wm * 64 + mt * 16 + gq;
            int cc = wn * 32 + nt * 8 + 2 * kr;
            float2 v01 = make_float2(acc[mt][nt][0], acc[mt][nt][1]);
            float2 v23 = make_float2(acc[mt][nt][2], acc[mt][nt][3]);
            *reinterpret_cast<float2*>(&op[(size_t)r * OW + cc]) = v01;
            *reinterpret_cast<float2*>(&op[(size_t)(r + 8) * OW + cc]) = v23;
        }
    }
}

// ---------------------------------------------------------------------------
// 3) Split-K reduce + gates + cell update + output concat
// ---------------------------------------------------------------------------
__global__ void gates_kernel(const float* __restrict__ c,
                             const float* __restrict__ ctx,
                             float* __restrict__ out) {
    int idx = blockIdx.x * blockDim.x + threadIdx.x;
    if (idx >= Bn * Un) return;
    int b = idx >> 11;
    int u = idx & (Un - 1);
    int n = u >> 9;
    int j = u & (UN - 1);
    const float* p0 = g_part + (size_t)b * OW + n * NW + j;
    const float* p1 = p0 + (size_t)Bn * OW;
    float iv = sigmoidf(p0[0]    + p1[0]);
    float fv = sigmoidf(p0[512]  + p1[512]);
    float gv = tanhf(   p0[1024] + p1[1024]);
    float ov = sigmoidf(p0[1536] + p1[1536]);
    float cv = c[idx];
    float nc = fv * cv + iv * gv;
    float nh = ov * tanhf(nc);
    out[HOUT_OFF + idx] = nh;
    out[COUT_OFF + idx] = nc;
    out[XOUT_OFF + b * (2 * Un) + u]      = nh;
    out[XOUT_OFF + b * (2 * Un) + Un + u] = ctx[idx];
}

// ---------------------------------------------------------------------------
// 4a) Attention scores: grid (128, 4), 256 threads; block does 128 l-rows.
// ---------------------------------------------------------------------------
__global__ void __launch_bounds__(256)
scores_kernel(const float* __restrict__ enc_attn,
              const float* __restrict__ out) {
    __shared__ float sh[Un];
    const int b   = blockIdx.x;
    const int lc  = blockIdx.y;
    const int tid = threadIdx.x;
    const int lane = tid & 31;
    const int warp = tid >> 5;      // 0..7

    const float4* hb = reinterpret_cast<const float4*>(out + HOUT_OFF + (size_t)b * Un);
    reinterpret_cast<float4*>(sh)[tid]       = hb[tid];
    reinterpret_cast<float4*>(sh)[tid + 256] = hb[tid + 256];
    __syncthreads();

    const float4* sh4 = reinterpret_cast<const float4*>(sh);
    const float* ea = enc_attn + (size_t)b * Ln * Un;
#pragma unroll 1
    for (int i = 0; i < 16; ++i) {
        int l = lc * 128 + warp * 16 + i;
        const float4* row = reinterpret_cast<const float4*>(ea + (size_t)l * Un);
        float s = 0.0f;
#pragma unroll 4
        for (int it = lane; it < Un / 4; it += 32) {
            float4 v = row[it];
            float4 hv = sh4[it];
            s += v.x * hv.x + v.y * hv.y + v.z * hv.z + v.w * hv.w;
        }
#pragma unroll
        for (int o = 16; o > 0; o >>= 1)
            s += __shfl_xor_sync(0xffffffffu, s, o);
        if (lane == 0) g_score[b * Ln + l] = s;
    }
}

// ---------------------------------------------------------------------------
// 4b) Softmax over 512 scores per batch row (in place in g_score)
// ---------------------------------------------------------------------------
__global__ void __launch_bounds__(512)
softmax_kernel() {
    __shared__ float red[16];
    __shared__ float red1;
    const int b = blockIdx.x;
    const int tid = threadIdx.x;
    const int lane = tid & 31;
    const int warp = tid >> 5;

    float v = g_score[b * Ln + tid];
    float m = v;
#pragma unroll
    for (int o = 16; o > 0; o >>= 1)
        m = fmaxf(m, __shfl_xor_sync(0xffffffffu, m, o));
    if (lane == 0) red[warp] = m;
    __syncthreads();
    if (tid == 0) {
        float mm = red[0];
#pragma unroll
        for (int i = 1; i < 16; ++i) mm = fmaxf(mm, red[i]);
        red1 = mm;
    }
    __syncthreads();
    float e = expf(v - red1);
    float s = e;
#pragma unroll
    for (int o = 16; o > 0; o >>= 1)
        s += __shfl_xor_sync(0xffffffffu, s, o);
    if (lane == 0) red[warp] = s;
    __syncthreads();
    if (tid == 0) {
        float ss = 0.0f;
#pragma unroll
        for (int i = 0; i < 16; ++i) ss += red[i];
        red1 = ss;
    }
    __syncthreads();
    g_score[b * Ln + tid] = e / red1;
}

// ---------------------------------------------------------------------------
// 4c) Weighted sum: grid (128, 4), 128 threads; block owns 512 u-columns.
// ---------------------------------------------------------------------------
__global__ void __launch_bounds__(128)
ctx_kernel(const float* __restrict__ enc_out,
           float* __restrict__ out) {
    __shared__ float w[Ln];
    const int b   = blockIdx.x;
    const int uc  = blockIdx.y;
    const int tid = threadIdx.x;

    reinterpret_cast<float4*>(w)[tid] =
        reinterpret_cast<const float4*>(g_score + (size_t)b * Ln)[tid];
    __syncthreads();

    const float* eo = enc_out + (size_t)b * Ln * Un + uc * 512 + tid * 4;
    float4 acc = make_float4(0.f, 0.f, 0.f, 0.f);
#pragma unroll 4
    for (int l = 0; l < Ln; ++l) {
        float ww = w[l];
        float4 vv = *reinterpret_cast<const float4*>(eo + (size_t)l * Un);
        acc.x = fmaf(ww, vv.x, acc.x);
        acc.y = fmaf(ww, vv.y, acc.y);
        acc.z = fmaf(ww, vv.z, acc.z);
        acc.w = fmaf(ww, vv.w, acc.w);
    }
    *reinterpret_cast<float4*>(out + CTX_OFF + (size_t)b * Un + uc * 512 + tid * 4) = acc;
}

// ---------------------------------------------------------------------------
extern "C" void kernel_launch(void* const* d_in, const int* in_sizes, int n_in,
                              void* d_out, int out_size) {
    const float* x        = (const float*)d_in[0];
    const float* h        = (const float*)d_in[1];
    const float* c        = (const float*)d_in[2];
    const float* context  = (const float*)d_in[3];
    const float* W        = (const float*)d_in[4];
    const float* enc_attn = (const float*)d_in[5];
    const float* enc_out  = (const float*)d_in[6];
    float* out = (float*)d_out;

    pack_xh_kernel<<<(Bn * KD + 255) / 256, 256>>>(x, h, context);
    gemm_tf32_kernel<<<dim3(OW / 128, 2), 256>>>(W);
    gates_kernel<<<(Bn * Un + 255) / 256, 256>>>(c, context, out);
    scores_kernel<<<dim3(Bn, 4), 256>>>(enc_attn, out);
    softmax_kernel<<<Bn, 512>>>();
    ctx_kernel<<<dim3(Bn, 4), 128>>>(enc_out, out);
}

// round 6
// speedup vs baseline: 1.8608x; 1.4687x over previous
#include <cuda_runtime.h>
#include <cuda_fp16.h>
#include <math.h>
#include <stdint.h>

// Problem constants
#define Bn   128
#define Un   2048
#define Kn   2
#define Nn   4
#define Ln   512
#define UK   (Un / Kn)        // 1024
#define UN   (Un / Nn)        // 512
#define XHW  (3 * UK)         // 3072
#define KD   (Kn * XHW)       // 6144
#define OW   (4 * Un)         // 8192
#define NW   (4 * UN)         // 2048

// Output layout
#define XOUT_OFF 0
#define HOUT_OFF (Bn * 2 * Un)
#define COUT_OFF (Bn * 3 * Un)
#define CTX_OFF  (Bn * 4 * Un)

// Scratch
__device__ __half g_xh_hi[Bn * KD];    // fp16 hi part
__device__ __half g_xh_lo[Bn * KD];    // fp16 (residual * 1024)
__device__ float g_part[Bn * OW];      // ifgo
__device__ float g_score[Bn * Ln];

__device__ __forceinline__ float sigmoidf(float v) {
    return 1.0f / (1.0f + expf(-v));
}

__device__ __forceinline__ uint32_t smem_u32(const void* p) {
    uint32_t a;
    asm("{ .reg .u64 t; cvta.to.shared.u64 t, %1; cvt.u32.u64 %0, t; }"
        : "=r"(a) : "l"(p));
    return a;
}

#define CP16(dst, src) \
    asm volatile("cp.async.cg.shared.global [%0], [%1], 16;" \
        :: "r"(dst), "l"(src))
#define CP_COMMIT() asm volatile("cp.async.commit_group;" ::: "memory")
#define CP_WAIT1()  asm volatile("cp.async.wait_group 1;" ::: "memory")

#define LDSM(r, a) \
    asm volatile("ldmatrix.sync.aligned.m8n8.x4.shared.b16 {%0,%1,%2,%3}, [%4];" \
        : "=r"((r)[0]), "=r"((r)[1]), "=r"((r)[2]), "=r"((r)[3]) : "r"(a))
#define LDSM_T(r, a) \
    asm volatile("ldmatrix.sync.aligned.m8n8.x4.trans.shared.b16 {%0,%1,%2,%3}, [%4];" \
        : "=r"((r)[0]), "=r"((r)[1]), "=r"((r)[2]), "=r"((r)[3]) : "r"(a))

__device__ __forceinline__ void mma_fp16(float* d, const uint32_t* a,
                                         uint32_t b0, uint32_t b1) {
    asm volatile(
        "mma.sync.aligned.m16n8k16.row.col.f32.f16.f16.f32 "
        "{%0,%1,%2,%3}, {%4,%5,%6,%7}, {%8,%9}, {%0,%1,%2,%3};\n"
        : "+f"(d[0]), "+f"(d[1]), "+f"(d[2]), "+f"(d[3])
        : "r"(a[0]), "r"(a[1]), "r"(a[2]), "r"(a[3]), "r"(b0), "r"(b1));
}

__device__ __forceinline__ uint32_t pack_h2(__half a, __half b) {
    uint32_t p;
    asm("mov.b32 %0, {%1, %2};" : "=r"(p)
        : "h"(__half_as_ushort(a)), "h"(__half_as_ushort(b)));
    return p;
}

// ---------------------------------------------------------------------------
// 1) Pack XH, split into fp16 hi + scaled lo
// ---------------------------------------------------------------------------
__global__ void pack_xh_kernel(const float* __restrict__ x,
                               const float* __restrict__ h,
                               const float* __restrict__ ctx) {
    int idx = blockIdx.x * blockDim.x + threadIdx.x;
    if (idx >= Bn * KD) return;
    int b  = idx / KD;
    int kd = idx - b * KD;
    int k  = kd / XHW;
    int d  = kd - k * XHW;
    int off = b * Un + k * UK;
    float v;
    if (d < UK)            v = h[off + d];
    else if (d < 2 * UK)   v = x[off + d - UK];
    else                   v = ctx[off + d - 2 * UK];
    __half hi = __float2half_rn(v);
    float rem = v - __half2float(hi);
    g_xh_hi[idx] = hi;
    g_xh_lo[idx] = __float2half_rn(rem * 1024.0f);
}

// ---------------------------------------------------------------------------
// 2) fp16 split GEMM on mma.sync.m16n8k16.
//    Per CTA: M=128, N=64, K=6144. Stage BK=32, double-buffered cp.async.
//    8 warps: 4 along M (32 rows), 2 along N (32 cols). acc 2x4 frags x2 terms.
// ---------------------------------------------------------------------------
#define BNC   64
#define BKS   32
#define NST   (KD / BKS)             // 192
#define A_STRIDE 80                  // bytes per A row (32 fp16 + pad)
#define ASZb  (128 * A_STRIDE)       // 10240
#define B_STRIDE 144                 // bytes per B k-row (64 fp16 + pad)
#define BSZb  (BKS * B_STRIDE)       // 4608
#define WRSZ  (BKS * BNC * 4)        // 8192 raw fp32 W staging
#define ST_AH 0
#define ST_AL ASZb
#define ST_BH (2 * ASZb)
#define ST_BL (2 * ASZb + BSZb)
#define ST_WR (2 * ASZb + 2 * BSZb)
#define STSZ  (2 * ASZb + 2 * BSZb + WRSZ)   // 37888
#define GSMEM (2 * STSZ)                     // 75776

__global__ void __launch_bounds__(256, 1)
gemm_fp16_kernel(const float* __restrict__ W) {
    extern __shared__ char smem[];
    const uint32_t sb = smem_u32(smem);
    const int tid  = threadIdx.x;
    const int lane = tid & 31;
    const int warp = tid >> 5;
    const int wm   = warp & 3;        // 0..3 -> rows wm*32
    const int wn   = warp >> 2;       // 0..1 -> cols wn*32

    const int col0 = blockIdx.x * BNC;
    const int n    = col0 >> 11;
    const int f0   = col0 & (NW - 1);

    float accm[2][4][4], accc[2][4][4];
#pragma unroll
    for (int i = 0; i < 2; ++i)
#pragma unroll
        for (int j = 0; j < 4; ++j)
#pragma unroll
            for (int q = 0; q < 4; ++q) { accm[i][j][q] = 0.f; accc[i][j][q] = 0.f; }

    // --- stage issue: cp.async A (pre-split fp16) + raw fp32 W ---
    auto issue = [&](int s) {
        const uint32_t stb = sb + (s & 1) * STSZ;
        const int k0 = s * BKS;
        {   // A: 128 rows x 32 fp16 (hi & lo); thread -> (row, 2 chunks)
            int r  = tid >> 1;
            int cb = (tid & 1) * 2;
            const __half* sh = g_xh_hi + (size_t)r * KD + k0 + cb * 8;
            const __half* sl = g_xh_lo + (size_t)r * KD + k0 + cb * 8;
            uint32_t da = stb + ST_AH + r * A_STRIDE + cb * 16;
            uint32_t dl = stb + ST_AL + r * A_STRIDE + cb * 16;
            CP16(da, sh);       CP16(da + 16, sh + 8);
            CP16(dl, sl);       CP16(dl + 16, sl + 8);
        }
        {   // W raw: 32 k-rows x 64 fp32
            int r  = tid >> 3;
            int c  = tid & 7;
            int kc = (k0 >= XHW) ? 1 : 0;
            int d  = k0 - kc * XHW + r;
            const float* src = W + ((size_t)(kc * Nn + n) * XHW + d) * (size_t)NW + f0;
            uint32_t dst = stb + ST_WR + r * 256;
            CP16(dst + c * 16,       src + c * 4);
            CP16(dst + (c + 8) * 16, src + (c + 8) * 4);
        }
    };

    // --- convert raw W -> fp16 hi/lo tiles [k][n] ---
    auto convert = [&](int s) {
        char* st = smem + (s & 1) * STSZ;
        int r  = tid >> 3;
        int c4 = tid & 7;
#pragma unroll
        for (int j = 0; j < 2; ++j) {
            int col = (c4 + 8 * j) * 4;
            float4 v = *reinterpret_cast<const float4*>(st + ST_WR + r * 256 + col * 4);
            __half hx = __float2half_rn(v.x), hy = __float2half_rn(v.y);
            __half hz = __float2half_rn(v.z), hw = __float2half_rn(v.w);
            __half lx = __float2half_rn((v.x - __half2float(hx)) * 1024.f);
            __half ly = __float2half_rn((v.y - __half2float(hy)) * 1024.f);
            __half lz = __float2half_rn((v.z - __half2float(hz)) * 1024.f);
            __half lw = __float2half_rn((v.w - __half2float(hw)) * 1024.f);
            *reinterpret_cast<uint2*>(st + ST_BH + r * B_STRIDE + col * 2) =
                make_uint2(pack_h2(hx, hy), pack_h2(hz, hw));
            *reinterpret_cast<uint2*>(st + ST_BL + r * B_STRIDE + col * 2) =
                make_uint2(pack_h2(lx, ly), pack_h2(lz, lw));
        }
    };

    // --- compute one stage (2 x k16 steps) ---
    auto compute = [&](int s) {
        const uint32_t stb = sb + (s & 1) * STSZ;
#pragma unroll
        for (int ks = 0; ks < 2; ++ks) {
            uint32_t bh[2][4], bl[2][4];
#pragma unroll
            for (int t = 0; t < 2; ++t) {
                uint32_t ba = stb + ST_BH + (ks * 16 + (lane & 15)) * B_STRIDE
                            + (wn * 32 + t * 16) * 2 + (lane >> 4) * 16;
                LDSM_T(bh[t], ba);
                LDSM_T(bl[t], ba + (ST_BL - ST_BH));
            }
#pragma unroll
            for (int mt = 0; mt < 2; ++mt) {
                uint32_t ah[4], al[4];
                uint32_t aa = stb + ST_AH
                            + (wm * 32 + mt * 16 + (lane & 15)) * A_STRIDE
                            + ks * 32 + (lane >> 4) * 16;
                LDSM(ah, aa);
                LDSM(al, aa + (ST_AL - ST_AH));
#pragma unroll
                for (int nt = 0; nt < 4; ++nt) {
                    int t = nt >> 1, g = (nt & 1) * 2;
                    mma_fp16(accm[mt][nt], ah, bh[t][g], bh[t][g + 1]);
                    mma_fp16(accc[mt][nt], ah, bl[t][g], bl[t][g + 1]);
                    mma_fp16(accc[mt][nt], al, bh[t][g], bh[t][g + 1]);
                }
            }
        }
    };

    issue(0);
    CP_COMMIT();
    for (int s = 0; s < NST; ++s) {
        if (s + 1 < NST) issue(s + 1);
        CP_COMMIT();
        CP_WAIT1();
        __syncthreads();
        convert(s);
        __syncthreads();
        compute(s);
        __syncthreads();
    }

    // Epilogue: D = main + corr / 1024
    const float isc = 1.0f / 1024.0f;
#pragma unroll
    for (int mt = 0; mt < 2; ++mt) {
#pragma unroll
        for (int nt = 0; nt < 4; ++nt) {
            int r  = wm * 32 + mt * 16 + (lane >> 2);
            int gc = col0 + wn * 32 + nt * 8 + (lane & 3) * 2;
            float2 v0, v1;
            v0.x = accm[mt][nt][0] + accc[mt][nt][0] * isc;
            v0.y = accm[mt][nt][1] + accc[mt][nt][1] * isc;
            v1.x = accm[mt][nt][2] + accc[mt][nt][2] * isc;
            v1.y = accm[mt][nt][3] + accc[mt][nt][3] * isc;
            *reinterpret_cast<float2*>(&g_part[(size_t)r * OW + gc]) = v0;
            *reinterpret_cast<float2*>(&g_part[(size_t)(r + 8) * OW + gc]) = v1;
        }
    }
}

// ---------------------------------------------------------------------------
// 3) Gates + cell update + output concat
// ---------------------------------------------------------------------------
__global__ void gates_kernel(const float* __restrict__ c,
                             const float* __restrict__ ctx,
                             float* __restrict__ out) {
    int idx = blockIdx.x * blockDim.x + threadIdx.x;
    if (idx >= Bn * Un) return;
    int b = idx >> 11;
    int u = idx & (Un - 1);
    int n = u >> 9;
    int j = u & (UN - 1);
    const float* p = g_part + (size_t)b * OW + n * NW + j;
    float iv = sigmoidf(p[0]);
    float fv = sigmoidf(p[512]);
    float gv = tanhf(p[1024]);
    float ov = sigmoidf(p[1536]);
    float cv = c[idx];
    float nc = fv * cv + iv * gv;
    float nh = ov * tanhf(nc);
    out[HOUT_OFF + idx] = nh;
    out[COUT_OFF + idx] = nc;
    out[XOUT_OFF + b * (2 * Un) + u]      = nh;
    out[XOUT_OFF + b * (2 * Un) + Un + u] = ctx[idx];
}

// ---------------------------------------------------------------------------
// 4a) Attention scores
// ---------------------------------------------------------------------------
__global__ void __launch_bounds__(256)
scores_kernel(const float* __restrict__ enc_attn,
              const float* __restrict__ out) {
    __shared__ float sh[Un];
    const int b   = blockIdx.x;
    const int lc  = blockIdx.y;
    const int tid = threadIdx.x;
    const int lane = tid & 31;
    const int warp = tid >> 5;

    const float4* hb = reinterpret_cast<const float4*>(out + HOUT_OFF + (size_t)b * Un);
    reinterpret_cast<float4*>(sh)[tid]       = hb[tid];
    reinterpret_cast<float4*>(sh)[tid + 256] = hb[tid + 256];
    __syncthreads();

    const float4* sh4 = reinterpret_cast<const float4*>(sh);
    const float* ea = enc_attn + (size_t)b * Ln * Un;
#pragma unroll 1
    for (int i = 0; i < 16; ++i) {
        int l = lc * 128 + warp * 16 + i;
        const float4* row = reinterpret_cast<const float4*>(ea + (size_t)l * Un);
        float s = 0.0f;
#pragma unroll 4
        for (int it = lane; it < Un / 4; it += 32) {
            float4 v = row[it];
            float4 hv = sh4[it];
            s += v.x * hv.x + v.y * hv.y + v.z * hv.z + v.w * hv.w;
        }
#pragma unroll
        for (int o = 16; o > 0; o >>= 1)
            s += __shfl_xor_sync(0xffffffffu, s, o);
        if (lane == 0) g_score[b * Ln + l] = s;
    }
}

// ---------------------------------------------------------------------------
// 4b) Softmax
// ---------------------------------------------------------------------------
__global__ void __launch_bounds__(512)
softmax_kernel() {
    __shared__ float red[16];
    __shared__ float red1;
    const int b = blockIdx.x;
    const int tid = threadIdx.x;
    const int lane = tid & 31;
    const int warp = tid >> 5;

    float v = g_score[b * Ln + tid];
    float m = v;
#pragma unroll
    for (int o = 16; o > 0; o >>= 1)
        m = fmaxf(m, __shfl_xor_sync(0xffffffffu, m, o));
    if (lane == 0) red[warp] = m;
    __syncthreads();
    if (tid == 0) {
        float mm = red[0];
#pragma unroll
        for (int i = 1; i < 16; ++i) mm = fmaxf(mm, red[i]);
        red1 = mm;
    }
    __syncthreads();
    float e = expf(v - red1);
    float s = e;
#pragma unroll
    for (int o = 16; o > 0; o >>= 1)
        s += __shfl_xor_sync(0xffffffffu, s, o);
    if (lane == 0) red[warp] = s;
    __syncthreads();
    if (tid == 0) {
        float ss = 0.0f;
#pragma unroll
        for (int i = 0; i < 16; ++i) ss += red[i];
        red1 = ss;
    }
    __syncthreads();
    g_score[b * Ln + tid] = e / red1;
}

// ---------------------------------------------------------------------------
// 4c) Weighted sum
// ---------------------------------------------------------------------------
__global__ void __launch_bounds__(128)
ctx_kernel(const float* __restrict__ enc_out,
           float* __restrict__ out) {
    __shared__ float w[Ln];
    const int b   = blockIdx.x;
    const int uc  = blockIdx.y;
    const int tid = threadIdx.x;

    reinterpret_cast<float4*>(w)[tid] =
        reinterpret_cast<const float4*>(g_score + (size_t)b * Ln)[tid];
    __syncthreads();

    const float* eo = enc_out + (size_t)b * Ln * Un + uc * 512 + tid * 4;
    float4 acc = make_float4(0.f, 0.f, 0.f, 0.f);
#pragma unroll 4
    for (int l = 0; l < Ln; ++l) {
        float ww = w[l];
        float4 vv = *reinterpret_cast<const float4*>(eo + (size_t)l * Un);
        acc.x = fmaf(ww, vv.x, acc.x);
        acc.y = fmaf(ww, vv.y, acc.y);
        acc.z = fmaf(ww, vv.z, acc.z);
        acc.w = fmaf(ww, vv.w, acc.w);
    }
    *reinterpret_cast<float4*>(out + CTX_OFF + (size_t)b * Un + uc * 512 + tid * 4) = acc;
}

// ---------------------------------------------------------------------------
extern "C" void kernel_launch(void* const* d_in, const int* in_sizes, int n_in,
                              void* d_out, int out_size) {
    const float* x        = (const float*)d_in[0];
    const float* h        = (const float*)d_in[1];
    const float* c        = (const float*)d_in[2];
    const float* context  = (const float*)d_in[3];
    const float* W        = (const float*)d_in[4];
    const float* enc_attn = (const float*)d_in[5];
    const float* enc_out  = (const float*)d_in[6];
    float* out = (float*)d_out;

    cudaFuncSetAttribute(gemm_fp16_kernel,
                         cudaFuncAttributeMaxDynamicSharedMemorySize, GSMEM);

    pack_xh_kernel<<<(Bn * KD + 255) / 256, 256>>>(x, h, context);
    gemm_fp16_kernel<<<OW / BNC, 256, GSMEM>>>(W);
    gates_kernel<<<(Bn * Un + 255) / 256, 256>>>(c, context, out);
    scores_kernel<<<dim3(Bn, 4), 256>>>(enc_attn, out);
    softmax_kernel<<<Bn, 512>>>();
    ctx_kernel<<<dim3(Bn, 4), 128>>>(enc_out, out);
}